// round 7
// baseline (speedup 1.0000x reference)
#include <cuda_runtime.h>

// FINAL — at the single-launch replay floor. Reference math collapses exactly:
//   p1 has feature dim 1  ->  mu == p1 (exact, mean over a singleton axis)
//   (p1 - mu) == 0 exactly -> var == 0 exactly
//   out = 0/sqrt(eps) * ln_weight + ln_bias = ln_bias  (for ANY x/params/ln_weight)
// So out[b] = ln_bias[0] for all b. ln_bias is read from device memory so the
// kernel is correct for arbitrary bias values, not just the test seed.
//
// Measured: wall 4.576 us is invariant across launch shapes (2x256, 1x128
// float4, 1x512); kernel node 3.3-3.7 us is launch overhead at idle clocks.
// No fewer-than-one-kernel formulation exists under graph-capture rules
// (memcpy can't broadcast, memset can't take a device value, host readback
// would require a sync). This is the floor.

__global__ __launch_bounds__(256, 1)
void QuantumGate_65481071410733_kernel(const float* __restrict__ ln_bias,
                                       float* __restrict__ out,
                                       int n) {
    int i = blockIdx.x * blockDim.x + threadIdx.x;
    if (i < n) {
        out[i] = __ldg(ln_bias);
    }
}

extern "C" void kernel_launch(void* const* d_in, const int* in_sizes, int n_in,
                              void* d_out, int out_size) {
    // Input order per metadata: x, params, ln_weight, ln_bias
    const float* ln_bias = (const float*)d_in[3];
    float* out = (float*)d_out;
    int n = out_size;  // 512
    QuantumGate_65481071410733_kernel<<<(n + 255) / 256, 256>>>(ln_bias, out, n);
}

// round 8
// speedup vs baseline: 1.0278x; 1.0278x over previous
#include <cuda_runtime.h>

// FINAL — at the single-launch replay floor. Reference math collapses exactly:
//   p1 has feature dim 1  ->  mu == p1 (exact, mean over a singleton axis)
//   (p1 - mu) == 0 exactly -> var == 0 exactly
//   out = 0/sqrt(eps) * ln_weight + ln_bias = ln_bias  (for ANY x/params/ln_weight)
// So out[b] = ln_bias[0] for all b. ln_bias is read from device memory so the
// kernel is correct for arbitrary bias values, not just the test seed.
//
// Variance note: this EXACT source measured 4.576 us (R6) and 5.920 us (R7)
// with identical kernel-node times (~3.65 us) — wall-time has ~±1.3 us
// harness-side noise uncorrelated with kernel content. Kernel node is
// shape-invariant at 3.3-3.7 us across 2x256 / 1x128-float4 / 1x512.
// No fewer-than-one-kernel formulation exists under graph-capture rules
// (memcpy can't broadcast, memset can't take a device value, host readback
// would require a sync). This is the floor; resubmitting unchanged.

__global__ __launch_bounds__(256, 1)
void QuantumGate_65481071410733_kernel(const float* __restrict__ ln_bias,
                                       float* __restrict__ out,
                                       int n) {
    int i = blockIdx.x * blockDim.x + threadIdx.x;
    if (i < n) {
        out[i] = __ldg(ln_bias);
    }
}

extern "C" void kernel_launch(void* const* d_in, const int* in_sizes, int n_in,
                              void* d_out, int out_size) {
    // Input order per metadata: x, params, ln_weight, ln_bias
    const float* ln_bias = (const float*)d_in[3];
    float* out = (float*)d_out;
    int n = out_size;  // 512
    QuantumGate_65481071410733_kernel<<<(n + 255) / 256, 256>>>(ln_bias, out, n);
}